// round 7
// baseline (speedup 1.0000x reference)
#include <cuda_runtime.h>
#include <cstdint>

// CRF_76501957476894 — CRF loss forward algorithm.
// B=512 batches, N=1024 timesteps, K=64 states.
// One warp per batch (128 CTAs x 128 thr). Lane l owns states (2l, 2l+1),
// alpha pair kept packed in one 64-bit register (apair = (alo, ahi)).
// Matvec broadcast: 64-bit SHFL.IDX of apair (2 SASS shfls, no pack MOV):
//   a_new[2l]   = (sum_s (a[2s],a[2s+1]) . (E[2s][2l],  E[2s+1][2l])  ) * em0*r
//   a_new[2l+1] = (sum_s (a[2s],a[2s+1]) . (E[2s][2l+1],E[2s+1][2l+1])) * em1*r
// Per-step renorm by lane-0's alpha (folded into next step's emit factor,
// off the critical chain). Scale log amortized: pv *= vcur per step,
// M += log(pv) every 4th step + final flush.

#define FULLMASK 0xFFFFFFFFu

__device__ __forceinline__ unsigned long long pk2(float x, float y) {
    unsigned long long r;
    asm("mov.b64 %0, {%1, %2};" : "=l"(r) : "f"(x), "f"(y));
    return r;
}
__device__ __forceinline__ void upk2(unsigned long long p, float &x, float &y) {
    asm("mov.b64 {%0, %1}, %2;" : "=f"(x), "=f"(y) : "l"(p));
}

// One forward step. EM0/EM1: raw exp(emit) for this lane's two states.
// Carried: apair (packed alpha), r (pending renorm scale), vcur (its source),
// pv (product of applied scales since last log), M (log offset).
#define STEP(EM0, EM1, DOLOG) do {                                                    \
    float em0r_ = (EM0) * r, em1r_ = (EM1) * r;                                       \
    pv *= vcur;                               /* scale applied this step */           \
    if (DOLOG) { M += __logf(pv); pv = 1.0f; }                                        \
    unsigned long long a00_=0ull, a01_=0ull, a10_=0ull, a11_=0ull;                    \
    _Pragma("unroll")                                                                 \
    for (int s_ = 0; s_ < 16; s_++) {                                                 \
        unsigned long long p_ = __shfl_sync(FULLMASK, apair, s_);                     \
        asm("fma.rn.f32x2 %0, %1, %2, %0;" : "+l"(a00_) : "l"(p_), "l"(EA[s_]));      \
        asm("fma.rn.f32x2 %0, %1, %2, %0;" : "+l"(a10_) : "l"(p_), "l"(EB[s_]));      \
    }                                                                                 \
    _Pragma("unroll")                                                                 \
    for (int s_ = 16; s_ < 32; s_++) {                                                \
        unsigned long long p_ = __shfl_sync(FULLMASK, apair, s_);                     \
        asm("fma.rn.f32x2 %0, %1, %2, %0;" : "+l"(a01_) : "l"(p_), "l"(EA[s_]));      \
        asm("fma.rn.f32x2 %0, %1, %2, %0;" : "+l"(a11_) : "l"(p_), "l"(EB[s_]));      \
    }                                                                                 \
    unsigned long long P_, Q_;                                                        \
    asm("add.rn.f32x2 %0, %1, %2;" : "=l"(P_) : "l"(a00_), "l"(a01_));                \
    asm("add.rn.f32x2 %0, %1, %2;" : "=l"(Q_) : "l"(a10_), "l"(a11_));                \
    float p0_, p1_, q0_, q1_;                                                         \
    upk2(P_, p0_, p1_); upk2(Q_, q0_, q1_);                                           \
    float alo_ = (p0_ + p1_) * em0r_;                                                 \
    float ahi_ = (q0_ + q1_) * em1r_;                                                 \
    apair = pk2(alo_, ahi_);                                                          \
    vcur = __shfl_sync(FULLMASK, alo_, 0);    /* renorm source for next step */       \
    asm("rcp.approx.f32 %0, %1;" : "=f"(r) : "f"(vcur));                              \
} while (0)

// Issue loads for timestep T into raw registers (no consumption here).
#define LOAD_T(T, ER, YR_) do {                                                       \
    (ER)  = *reinterpret_cast<const float2*>(yp + (size_t)(T) * 64 + 2 * l);          \
    (YR_) = __ldg(yr + (T));                                                          \
} while (0)

// Process previously-loaded raws: fold point/trans scores, compute exp(emit).
// ts uses a warp-uniform broadcast LDS (all lanes accumulate identically).
#define PROC_T(ER, YR_, D0, D1) do {                                                  \
    point += (((YR_) >> 1) == l) ? (((YR_) & 1) ? (ER).y : (ER).x) : 0.0f;            \
    ts += tsh[yprev * 64 + (YR_)];                                                    \
    yprev = (YR_);                                                                    \
    (D0) = __expf((ER).x);                                                            \
    (D1) = __expf((ER).y);                                                            \
} while (0)

__global__ void __launch_bounds__(128, 1) crf_fwd_kernel(
    const float* __restrict__ y_pred,   // [512,1024,64]
    const float* __restrict__ trans,    // [64,64]
    const int*   __restrict__ y_true,   // [512,1024]
    float*       __restrict__ out)      // [512]
{
    __shared__ float tsh[64 * 64];

    const int tid = threadIdx.x;
    const int w = tid >> 5;
    const int l = tid & 31;

    for (int i = tid; i < 4096; i += 128) tsh[i] = trans[i];
    __syncthreads();

    const int b = blockIdx.x * 4 + w;
    const float* yp = y_pred + (size_t)b * (1024 * 64);
    const int*   yr = y_true + b * 1024;

    // EA[s] = (exp(trans[2s][2l]),   exp(trans[2s+1][2l]))
    // EB[s] = (exp(trans[2s][2l+1]), exp(trans[2s+1][2l+1]))    (128 regs)
    unsigned long long EA[32], EB[32];
    #pragma unroll
    for (int s = 0; s < 32; s++) {
        EA[s] = pk2(__expf(tsh[(2 * s) * 64 + 2 * l]),
                    __expf(tsh[(2 * s + 1) * 64 + 2 * l]));
        EB[s] = pk2(__expf(tsh[(2 * s) * 64 + 2 * l + 1]),
                    __expf(tsh[(2 * s + 1) * 64 + 2 * l + 1]));
    }

    // ---- t = 0 init ----
    float2 e0v = *reinterpret_cast<const float2*>(yp + 2 * l);
    int yprev = __ldg(yr);
    float point = ((yprev >> 1) == l) ? ((yprev & 1) ? e0v.y : e0v.x) : 0.0f;
    float ts = 0.0f;   // trans score: warp-uniform accumulation.
    unsigned long long apair = pk2(__expf(e0v.x), __expf(e0v.y));
    float M = 0.0f, r = 1.0f, vcur = 1.0f, pv = 1.0f;

    // Pipeline: raw = loads of next group to process; ee = ems ready for STEP.
    float2 raw[4];
    int    yraw[4];
    float  ee0[4], ee1[4];

    // Prologue: load G0 (t=1..4); process G0; load G1 (t=5..8).
    #pragma unroll
    for (int k = 0; k < 4; k++) LOAD_T(1 + k, raw[k], yraw[k]);
    #pragma unroll
    for (int k = 0; k < 4; k++) PROC_T(raw[k], yraw[k], ee0[k], ee1[k]);
    #pragma unroll
    for (int k = 0; k < 4; k++) LOAD_T(5 + k, raw[k], yraw[k]);

    // ---- main loop: 253 iters. Iter g: process G_{g+1}, load G_{g+2}
    //      (max t = 1020, always in bounds), step group G_g, rotate. ----
    #pragma unroll 1
    for (int g = 0; g < 253; ++g) {
        float en0[4], en1[4];
        #pragma unroll
        for (int k = 0; k < 4; k++) PROC_T(raw[k], yraw[k], en0[k], en1[k]);
        const int tb = 9 + 4 * g;
        #pragma unroll
        for (int k = 0; k < 4; k++) LOAD_T(tb + k, raw[k], yraw[k]);
        STEP(ee0[0], ee1[0], false);
        STEP(ee0[1], ee1[1], false);
        STEP(ee0[2], ee1[2], false);
        STEP(ee0[3], ee1[3], true);     // amortized log every 4 steps
        #pragma unroll
        for (int k = 0; k < 4; k++) { ee0[k] = en0[k]; ee1[k] = en1[k]; }
    }

    // ---- epilogue 1: ee = G253 (t=1013..1016), raw = G254 loads ----
    float en0[4], en1[4];
    #pragma unroll
    for (int k = 0; k < 4; k++) PROC_T(raw[k], yraw[k], en0[k], en1[k]);
    float2 rt3[3]; int yt3[3];
    #pragma unroll
    for (int k = 0; k < 3; k++) LOAD_T(1021 + k, rt3[k], yt3[k]);
    STEP(ee0[0], ee1[0], false);
    STEP(ee0[1], ee1[1], false);
    STEP(ee0[2], ee1[2], false);
    STEP(ee0[3], ee1[3], true);

    // ---- epilogue 2: G254 (t=1017..1020); process tail ----
    float et0[3], et1[3];
    #pragma unroll
    for (int k = 0; k < 3; k++) PROC_T(rt3[k], yt3[k], et0[k], et1[k]);
    STEP(en0[0], en1[0], false);
    STEP(en0[1], en1[1], false);
    STEP(en0[2], en1[2], false);
    STEP(en0[3], en1[3], true);

    // ---- tail: t = 1021..1023 ----
    STEP(et0[0], et1[0], false);
    STEP(et0[1], et1[1], false);
    STEP(et0[2], et1[2], false);

    // ---- finalize: flush scales applied since last log (tail steps) ----
    M += __logf(pv);
    float alo_f, ahi_f;
    upk2(apair, alo_f, ahi_f);
    float s = alo_f + ahi_f;
    #pragma unroll
    for (int o = 16; o > 0; o >>= 1) s += __shfl_xor_sync(FULLMASK, s, o);
    float log_norm = M + __logf(s);

    #pragma unroll
    for (int o = 16; o > 0; o >>= 1) point += __shfl_xor_sync(FULLMASK, point, o);

    if (l == 0) out[b] = log_norm - (point + ts);
}

extern "C" void kernel_launch(void* const* d_in, const int* in_sizes, int n_in,
                              void* d_out, int out_size) {
    const float* y_pred = (const float*)d_in[0];   // [512,1024,64] f32
    const float* trans  = (const float*)d_in[1];   // [64,64] f32
    const int*   y_true = (const int*)d_in[2];     // [512,1024] i32
    float* out = (float*)d_out;                    // [512] f32
    (void)in_sizes; (void)n_in; (void)out_size;
    crf_fwd_kernel<<<128, 128>>>(y_pred, trans, y_true, out);
}

// round 13
// speedup vs baseline: 1.4165x; 1.4165x over previous
#include <cuda_runtime.h>
#include <cstdint>

// CRF_76501957476894 — CRF loss forward algorithm.
// B=512 batches, N=1024 timesteps, K=64 states.
// One warp per batch (128 CTAs x 128 thr). Lane l owns states (2l, 2l+1).
// Alpha vector stored UN-duplicated in shared (256B, double buffered).
// Matvec: 16x ld.shared.v2.b64 broadcast -> natural pairs (a[2s],a[2s+1]);
//   EA[s] = (E[2s][2l],  E[2s+1][2l]),  EB[s] = (E[2s][2l+1], E[2s+1][2l+1])
// 8-way accumulator split (4 per output) -> 8-deep FMA chains (32 cyc).
// NO shuffles / extra loads for renorm: scale source a_prev[0] is extracted
// from the first vector load's low word; log amortized (pv, log / 4 steps).

#define FULLMASK 0xFFFFFFFFu

__device__ __forceinline__ unsigned long long pk2(float x, float y) {
    unsigned long long r;
    asm("mov.b64 %0, {%1, %2};" : "=l"(r) : "f"(x), "f"(y));
    return r;
}
__device__ __forceinline__ void upk2(unsigned long long p, float &x, float &y) {
    asm("mov.b64 {%0, %1}, %2;" : "=f"(x), "=f"(y) : "l"(p));
}
__device__ __forceinline__ float lo32(unsigned long long p) {
    float x, y;
    asm("mov.b64 {%0, %1}, %2;" : "=f"(x), "=f"(y) : "l"(p));
    (void)y;
    return x;
}

// One forward step. EM0/EM1: raw exp(emit) for this lane's two states.
// Reads a_{t-1} (unnormalized) from RB, writes a_t to WB.
// Scale r = 1/a_{t-1}[0] (extracted from first vector load) folded into the
// emit factors; pv accumulates applied scales, M += log(pv) on DOLOG steps.
#define STEP(EM0, EM1, RB, WB, DOLOG) do {                                            \
    unsigned long long accA_[4] = {0ull,0ull,0ull,0ull};                              \
    unsigned long long accB_[4] = {0ull,0ull,0ull,0ull};                              \
    float vcur_, r_, em0r_, em1r_;                                                    \
    _Pragma("unroll")                                                                 \
    for (int h_ = 0; h_ < 4; h_++) {            /* s-block h_: s = 8h_..8h_+7 */      \
        unsigned long long p_[8];                                                     \
        _Pragma("unroll")                                                             \
        for (int u_ = 0; u_ < 4; u_++)                                                \
            asm volatile("ld.shared.v2.b64 {%0,%1}, [%2];"                            \
                : "=l"(p_[2*u_]), "=l"(p_[2*u_+1])                                    \
                : "r"((RB) + 64u * h_ + 16u * u_));                                   \
        if (h_ == 0) {                                                                \
            vcur_ = lo32(p_[0]);                  /* a_{t-1}[0], all lanes */         \
            asm("rcp.approx.f32 %0, %1;" : "=f"(r_) : "f"(vcur_));                    \
            em0r_ = (EM0) * r_; em1r_ = (EM1) * r_;                                   \
        }                                                                             \
        _Pragma("unroll")                                                             \
        for (int j_ = 0; j_ < 8; j_++) {                                              \
            asm("fma.rn.f32x2 %0, %1, %2, %0;"                                        \
                : "+l"(accA_[h_]) : "l"(p_[j_]), "l"(EA[8*h_+j_]));                   \
            asm("fma.rn.f32x2 %0, %1, %2, %0;"                                        \
                : "+l"(accB_[h_]) : "l"(p_[j_]), "l"(EB[8*h_+j_]));                   \
        }                                                                             \
    }                                                                                 \
    pv *= vcur_;                                                                      \
    if (DOLOG) { M += __logf(pv); pv = 1.0f; }                                        \
    unsigned long long A01_, A23_, P_, B01_, B23_, Q_;                                \
    asm("add.rn.f32x2 %0, %1, %2;" : "=l"(A01_) : "l"(accA_[0]), "l"(accA_[1]));      \
    asm("add.rn.f32x2 %0, %1, %2;" : "=l"(A23_) : "l"(accA_[2]), "l"(accA_[3]));      \
    asm("add.rn.f32x2 %0, %1, %2;" : "=l"(P_)   : "l"(A01_),     "l"(A23_));          \
    asm("add.rn.f32x2 %0, %1, %2;" : "=l"(B01_) : "l"(accB_[0]), "l"(accB_[1]));      \
    asm("add.rn.f32x2 %0, %1, %2;" : "=l"(B23_) : "l"(accB_[2]), "l"(accB_[3]));      \
    asm("add.rn.f32x2 %0, %1, %2;" : "=l"(Q_)   : "l"(B01_),     "l"(B23_));          \
    float p0_, p1_, q0_, q1_;                                                         \
    upk2(P_, p0_, p1_); upk2(Q_, q0_, q1_);                                           \
    alo = (p0_ + p1_) * em0r_;                                                        \
    ahi = (q0_ + q1_) * em1r_;                                                        \
    asm volatile("st.shared.b64 [%0], %1;" :: "r"((WB) + 8u * l),                     \
                 "l"(pk2(alo, ahi)));                                                 \
    __syncwarp();                                                                     \
} while (0)

// Issue loads for timestep T into raw registers (no consumption here).
#define LOAD_T(T, ER, YR_) do {                                                       \
    (ER)  = *reinterpret_cast<const float2*>(yp + (size_t)(T) * 64 + 2 * l);          \
    (YR_) = __ldg(yr + (T));                                                          \
} while (0)

// Process previously-loaded raws: fold point/trans scores, compute exp(emit).
// ts uses a warp-uniform broadcast LDS (all lanes accumulate identically).
#define PROC_T(ER, YR_, D0, D1) do {                                                  \
    point += (((YR_) >> 1) == l) ? (((YR_) & 1) ? (ER).y : (ER).x) : 0.0f;            \
    ts += tsh[yprev * 64 + (YR_)];                                                    \
    yprev = (YR_);                                                                    \
    (D0) = __expf((ER).x);                                                            \
    (D1) = __expf((ER).y);                                                            \
} while (0)

__global__ void __launch_bounds__(128, 1) crf_fwd_kernel(
    const float* __restrict__ y_pred,   // [512,1024,64]
    const float* __restrict__ trans,    // [64,64]
    const int*   __restrict__ y_true,   // [512,1024]
    float*       __restrict__ out)      // [512]
{
    __shared__ float tsh[64 * 64];
    __shared__ unsigned long long abuf[4][2][32];   // per-warp double buffer, 256B each

    const int tid = threadIdx.x;
    const int w = tid >> 5;
    const int l = tid & 31;

    for (int i = tid; i < 4096; i += 128) tsh[i] = trans[i];
    __syncthreads();

    const int b = blockIdx.x * 4 + w;
    const float* yp = y_pred + (size_t)b * (1024 * 64);
    const int*   yr = y_true + b * 1024;

    // EA[s] = (exp(trans[2s][2l]),   exp(trans[2s+1][2l]))
    // EB[s] = (exp(trans[2s][2l+1]), exp(trans[2s+1][2l+1]))    (128 regs)
    unsigned long long EA[32], EB[32];
    #pragma unroll
    for (int s = 0; s < 32; s++) {
        EA[s] = pk2(__expf(tsh[(2 * s) * 64 + 2 * l]),
                    __expf(tsh[(2 * s + 1) * 64 + 2 * l]));
        EB[s] = pk2(__expf(tsh[(2 * s) * 64 + 2 * l + 1]),
                    __expf(tsh[(2 * s + 1) * 64 + 2 * l + 1]));
    }

    const uint32_t shbase = (uint32_t)__cvta_generic_to_shared(&abuf[w][0][0]);
    const uint32_t buf0 = shbase;
    const uint32_t buf1 = shbase + 256u;

    // ---- t = 0 init ----
    float2 e0v = *reinterpret_cast<const float2*>(yp + 2 * l);
    int yprev = __ldg(yr);
    float point = ((yprev >> 1) == l) ? ((yprev & 1) ? e0v.y : e0v.x) : 0.0f;
    float ts = 0.0f;   // trans score: warp-uniform accumulation.
    float alo = __expf(e0v.x);
    float ahi = __expf(e0v.y);
    float M = 0.0f, pv = 1.0f;
    asm volatile("st.shared.b64 [%0], %1;" :: "r"(buf0 + 8u * l), "l"(pk2(alo, ahi)));
    __syncwarp();

    // Pipeline: raw = loads of next group to process; ee = ems ready for STEP.
    float2 raw[4];
    int    yraw[4];
    float  ee0[4], ee1[4];

    // Prologue: load G0 (t=1..4); process G0; load G1 (t=5..8).
    #pragma unroll
    for (int k = 0; k < 4; k++) LOAD_T(1 + k, raw[k], yraw[k]);
    #pragma unroll
    for (int k = 0; k < 4; k++) PROC_T(raw[k], yraw[k], ee0[k], ee1[k]);
    #pragma unroll
    for (int k = 0; k < 4; k++) LOAD_T(5 + k, raw[k], yraw[k]);

    // ---- main loop: 253 iters. Iter g: process G_{g+1}, load G_{g+2}
    //      (max t = 1020, always in bounds), step group G_g, rotate. ----
    #pragma unroll 1
    for (int g = 0; g < 253; ++g) {
        float en0[4], en1[4];
        #pragma unroll
        for (int k = 0; k < 4; k++) PROC_T(raw[k], yraw[k], en0[k], en1[k]);
        const int tb = 9 + 4 * g;
        #pragma unroll
        for (int k = 0; k < 4; k++) LOAD_T(tb + k, raw[k], yraw[k]);
        STEP(ee0[0], ee1[0], buf0, buf1, false);
        STEP(ee0[1], ee1[1], buf1, buf0, false);
        STEP(ee0[2], ee1[2], buf0, buf1, false);
        STEP(ee0[3], ee1[3], buf1, buf0, true);     // amortized log every 4 steps
        #pragma unroll
        for (int k = 0; k < 4; k++) { ee0[k] = en0[k]; ee1[k] = en1[k]; }
    }

    // ---- epilogue 1: ee = G253 (t=1013..1016), raw = G254 loads ----
    float en0[4], en1[4];
    #pragma unroll
    for (int k = 0; k < 4; k++) PROC_T(raw[k], yraw[k], en0[k], en1[k]);
    float2 rt3[3]; int yt3[3];
    #pragma unroll
    for (int k = 0; k < 3; k++) LOAD_T(1021 + k, rt3[k], yt3[k]);
    STEP(ee0[0], ee1[0], buf0, buf1, false);
    STEP(ee0[1], ee1[1], buf1, buf0, false);
    STEP(ee0[2], ee1[2], buf0, buf1, false);
    STEP(ee0[3], ee1[3], buf1, buf0, true);

    // ---- epilogue 2: G254 (t=1017..1020); process tail ----
    float et0[3], et1[3];
    #pragma unroll
    for (int k = 0; k < 3; k++) PROC_T(rt3[k], yt3[k], et0[k], et1[k]);
    STEP(en0[0], en1[0], buf0, buf1, false);
    STEP(en0[1], en1[1], buf1, buf0, false);
    STEP(en0[2], en1[2], buf0, buf1, false);
    STEP(en0[3], en1[3], buf1, buf0, true);

    // ---- tail: t = 1021..1023 ----
    STEP(et0[0], et1[0], buf0, buf1, false);
    STEP(et0[1], et1[1], buf1, buf0, false);
    STEP(et0[2], et1[2], buf0, buf1, false);

    // ---- finalize: flush scales applied since last log (tail steps) ----
    M += __logf(pv);
    float s = alo + ahi;
    #pragma unroll
    for (int o = 16; o > 0; o >>= 1) s += __shfl_xor_sync(FULLMASK, s, o);
    float log_norm = M + __logf(s);

    #pragma unroll
    for (int o = 16; o > 0; o >>= 1) point += __shfl_xor_sync(FULLMASK, point, o);

    if (l == 0) out[b] = log_norm - (point + ts);
}

extern "C" void kernel_launch(void* const* d_in, const int* in_sizes, int n_in,
                              void* d_out, int out_size) {
    const float* y_pred = (const float*)d_in[0];   // [512,1024,64] f32
    const float* trans  = (const float*)d_in[1];   // [64,64] f32
    const int*   y_true = (const int*)d_in[2];     // [512,1024] i32
    float* out = (float*)d_out;                    // [512] f32
    (void)in_sizes; (void)n_in; (void)out_size;
    crf_fwd_kernel<<<128, 128>>>(y_pred, trans, y_true, out);
}

// round 15
// speedup vs baseline: 2.0669x; 1.4591x over previous
#include <cuda_runtime.h>
#include <cstdint>

// CRF_76501957476894 — bidirectional CRF forward algorithm.
// B=512, N=1024, K=64. Z factors at the midpoint:
//   Z = alpha_512^T * E * c_513,
//   alpha_t = em_t ⊙ (E^T alpha_{t-1})   (forward, 512 steps + 1 plain matvec)
//   c_t     = em_t ⊙ (E   c_{t+1})       (backward, 510 steps, c_1023 = em_1023)
// Both chains have IDENTICAL matvec structure (E packed col-major for fwd,
// row-major for bwd). 256 CTAs x 128 thr: warps 0,1 = fwd for batches 2c,2c+1;
// warps 2,3 = bwd. Serial depth halves: 1023 -> ~512 steps.
// Per-warp step: un-duplicated shared alpha (256B double buffer), 16x
// ld.shared.v2.b64 broadcast, 8-way split f32x2 accumulators, renorm scale
// from first vector load's low word, log amortized every 4 steps.

#define FULLMASK 0xFFFFFFFFu

__device__ __forceinline__ unsigned long long pk2(float x, float y) {
    unsigned long long r;
    asm("mov.b64 %0, {%1, %2};" : "=l"(r) : "f"(x), "f"(y));
    return r;
}
__device__ __forceinline__ void upk2(unsigned long long p, float &x, float &y) {
    asm("mov.b64 {%0, %1}, %2;" : "=f"(x), "=f"(y) : "l"(p));
}
__device__ __forceinline__ float lo32(unsigned long long p) {
    float x, y;
    asm("mov.b64 {%0, %1}, %2;" : "=f"(x), "=f"(y) : "l"(p));
    (void)y;
    return x;
}

// One chain step (same for fwd/bwd; packing differences live in EA/EB init).
#define STEP(EM0, EM1, RB, WB, DOLOG) do {                                            \
    unsigned long long accA_[4] = {0ull,0ull,0ull,0ull};                              \
    unsigned long long accB_[4] = {0ull,0ull,0ull,0ull};                              \
    float vcur_, r_, em0r_, em1r_;                                                    \
    _Pragma("unroll")                                                                 \
    for (int h_ = 0; h_ < 4; h_++) {                                                  \
        unsigned long long p_[8];                                                     \
        _Pragma("unroll")                                                             \
        for (int u_ = 0; u_ < 4; u_++)                                                \
            asm volatile("ld.shared.v2.b64 {%0,%1}, [%2];"                            \
                : "=l"(p_[2*u_]), "=l"(p_[2*u_+1])                                    \
                : "r"((RB) + 64u * h_ + 16u * u_));                                   \
        if (h_ == 0) {                                                                \
            vcur_ = lo32(p_[0]);                                                      \
            asm("rcp.approx.f32 %0, %1;" : "=f"(r_) : "f"(vcur_));                    \
            em0r_ = (EM0) * r_; em1r_ = (EM1) * r_;                                   \
        }                                                                             \
        _Pragma("unroll")                                                             \
        for (int j_ = 0; j_ < 8; j_++) {                                              \
            asm("fma.rn.f32x2 %0, %1, %2, %0;"                                        \
                : "+l"(accA_[h_]) : "l"(p_[j_]), "l"(EA[8*h_+j_]));                   \
            asm("fma.rn.f32x2 %0, %1, %2, %0;"                                        \
                : "+l"(accB_[h_]) : "l"(p_[j_]), "l"(EB[8*h_+j_]));                   \
        }                                                                             \
    }                                                                                 \
    pv *= vcur_;                                                                      \
    if (DOLOG) { M += __logf(pv); pv = 1.0f; }                                        \
    unsigned long long A01_, A23_, P_, B01_, B23_, Q_;                                \
    asm("add.rn.f32x2 %0, %1, %2;" : "=l"(A01_) : "l"(accA_[0]), "l"(accA_[1]));      \
    asm("add.rn.f32x2 %0, %1, %2;" : "=l"(A23_) : "l"(accA_[2]), "l"(accA_[3]));      \
    asm("add.rn.f32x2 %0, %1, %2;" : "=l"(P_)   : "l"(A01_),     "l"(A23_));          \
    asm("add.rn.f32x2 %0, %1, %2;" : "=l"(B01_) : "l"(accB_[0]), "l"(accB_[1]));      \
    asm("add.rn.f32x2 %0, %1, %2;" : "=l"(B23_) : "l"(accB_[2]), "l"(accB_[3]));      \
    asm("add.rn.f32x2 %0, %1, %2;" : "=l"(Q_)   : "l"(B01_),     "l"(B23_));          \
    float p0_, p1_, q0_, q1_;                                                         \
    upk2(P_, p0_, p1_); upk2(Q_, q0_, q1_);                                           \
    alo = (p0_ + p1_) * em0r_;                                                        \
    ahi = (q0_ + q1_) * em1r_;                                                        \
    asm volatile("st.shared.b64 [%0], %1;" :: "r"((WB) + 8u * l),                     \
                 "l"(pk2(alo, ahi)));                                                 \
    __syncwarp();                                                                     \
} while (0)

#define LOAD_T(T, ER, YR_) do {                                                       \
    (ER)  = *reinterpret_cast<const float2*>(yp + (size_t)(T) * 64 + 2 * l);          \
    (YR_) = __ldg(yr + (T));                                                          \
} while (0)

// Forward proc: trans pair (y_{t-1}, y_t) = tsh[yprev][yt].
#define PROC_F(ER, YR_, D0, D1) do {                                                  \
    point += (((YR_) >> 1) == l) ? (((YR_) & 1) ? (ER).y : (ER).x) : 0.0f;            \
    ts += tsh[yprev * 64 + (YR_)];                                                    \
    yprev = (YR_);                                                                    \
    (D0) = __expf((ER).x);                                                            \
    (D1) = __expf((ER).y);                                                            \
} while (0)

// Backward proc (t descending): trans pair (y_t, y_{t+1}) = tsh[yt][yprev].
#define PROC_B(ER, YR_, D0, D1) do {                                                  \
    point += (((YR_) >> 1) == l) ? (((YR_) & 1) ? (ER).y : (ER).x) : 0.0f;            \
    ts += tsh[(YR_) * 64 + yprev];                                                    \
    yprev = (YR_);                                                                    \
    (D0) = __expf((ER).x);                                                            \
    (D1) = __expf((ER).y);                                                            \
} while (0)

__global__ void __launch_bounds__(128, 2) crf_fwd_kernel(
    const float* __restrict__ y_pred,   // [512,1024,64]
    const float* __restrict__ trans,    // [64,64]
    const int*   __restrict__ y_true,   // [512,1024]
    float*       __restrict__ out)      // [512]
{
    __shared__ float tsh[64 * 64];
    __shared__ unsigned long long abuf[4][2][32];   // per-warp double buffer
    __shared__ unsigned long long resbuf[4][32];    // per-warp final vector
    __shared__ float sM[4], sSc[4];                 // per-warp scale-log / score

    const int tid = threadIdx.x;
    const int w = tid >> 5;
    const int l = tid & 31;

    for (int i = tid; i < 4096; i += 128) tsh[i] = trans[i];
    __syncthreads();

    const int  b   = blockIdx.x * 2 + (w & 1);
    const bool dfw = (w < 2);                       // warp role (warp-uniform)
    const float* yp = y_pred + (size_t)b * (1024 * 64);
    const int*   yr = y_true + b * 1024;

    // E packing: fwd col-major pairs, bwd row-major pairs. 128 regs.
    unsigned long long EA[32], EB[32];
    #pragma unroll
    for (int s = 0; s < 32; s++) {
        if (dfw) {
            EA[s] = pk2(__expf(tsh[(2 * s) * 64 + 2 * l]),
                        __expf(tsh[(2 * s + 1) * 64 + 2 * l]));
            EB[s] = pk2(__expf(tsh[(2 * s) * 64 + 2 * l + 1]),
                        __expf(tsh[(2 * s + 1) * 64 + 2 * l + 1]));
        } else {
            EA[s] = pk2(__expf(tsh[(2 * l) * 64 + 2 * s]),
                        __expf(tsh[(2 * l) * 64 + 2 * s + 1]));
            EB[s] = pk2(__expf(tsh[(2 * l + 1) * 64 + 2 * s]),
                        __expf(tsh[(2 * l + 1) * 64 + 2 * s + 1]));
        }
    }

    const uint32_t shbase = (uint32_t)__cvta_generic_to_shared(&abuf[w][0][0]);
    const uint32_t buf0 = shbase;
    const uint32_t buf1 = shbase + 256u;

    float point, ts = 0.0f, alo, ahi, M = 0.0f, pv = 1.0f;
    int yprev;
    float2 raw[4];
    int    yraw[4];
    float  ee0[4], ee1[4], en0[4], en1[4];

    if (dfw) {
        // ---------- FORWARD: alpha, t = 0 .. 512, + 1 plain matvec ----------
        float2 e0 = *reinterpret_cast<const float2*>(yp + 2 * l);
        yprev = __ldg(yr);
        point = ((yprev >> 1) == l) ? ((yprev & 1) ? e0.y : e0.x) : 0.0f;
        alo = __expf(e0.x); ahi = __expf(e0.y);
        asm volatile("st.shared.b64 [%0], %1;" :: "r"(buf0 + 8u * l), "l"(pk2(alo, ahi)));
        __syncwarp();

        #pragma unroll
        for (int k = 0; k < 4; k++) LOAD_T(1 + k, raw[k], yraw[k]);
        #pragma unroll
        for (int k = 0; k < 4; k++) PROC_F(raw[k], yraw[k], ee0[k], ee1[k]);
        #pragma unroll
        for (int k = 0; k < 4; k++) LOAD_T(5 + k, raw[k], yraw[k]);

        // 126 iters: steps G0..G125 (t=1..504); loads G2..G127 (t<=512).
        #pragma unroll 1
        for (int g = 0; g < 126; ++g) {
            #pragma unroll
            for (int k = 0; k < 4; k++) PROC_F(raw[k], yraw[k], en0[k], en1[k]);
            const int tb = 9 + 4 * g;
            #pragma unroll
            for (int k = 0; k < 4; k++) LOAD_T(tb + k, raw[k], yraw[k]);
            STEP(ee0[0], ee1[0], buf0, buf1, false);
            STEP(ee0[1], ee1[1], buf1, buf0, false);
            STEP(ee0[2], ee1[2], buf0, buf1, false);
            STEP(ee0[3], ee1[3], buf1, buf0, true);
            #pragma unroll
            for (int k = 0; k < 4; k++) { ee0[k] = en0[k]; ee1[k] = en1[k]; }
        }
        // ee = G126 (t=505..508); raws = G127 (t=509..512).
        #pragma unroll
        for (int k = 0; k < 4; k++) PROC_F(raw[k], yraw[k], en0[k], en1[k]);
        STEP(ee0[0], ee1[0], buf0, buf1, false);
        STEP(ee0[1], ee1[1], buf1, buf0, false);
        STEP(ee0[2], ee1[2], buf0, buf1, false);
        STEP(ee0[3], ee1[3], buf1, buf0, true);
        STEP(en0[0], en1[0], buf0, buf1, false);
        STEP(en0[1], en1[1], buf1, buf0, false);
        STEP(en0[2], en1[2], buf0, buf1, false);
        STEP(en0[3], en1[3], buf1, buf0, true);
        // extra plain matvec (em = 1): d = alpha_512^T E  (scaled; in pv/M)
        STEP(1.0f, 1.0f, buf0, buf1, false);
    } else {
        // ---------- BACKWARD: c_t, t = 1022 .. 513; c_1023 = em_1023 ----------
        float2 e0 = *reinterpret_cast<const float2*>(yp + (size_t)1023 * 64 + 2 * l);
        yprev = __ldg(yr + 1023);
        point = ((yprev >> 1) == l) ? ((yprev & 1) ? e0.y : e0.x) : 0.0f;
        alo = __expf(e0.x); ahi = __expf(e0.y);
        asm volatile("st.shared.b64 [%0], %1;" :: "r"(buf0 + 8u * l), "l"(pk2(alo, ahi)));
        __syncwarp();

        #pragma unroll
        for (int k = 0; k < 4; k++) LOAD_T(1022 - k, raw[k], yraw[k]);
        #pragma unroll
        for (int k = 0; k < 4; k++) PROC_B(raw[k], yraw[k], ee0[k], ee1[k]);
        #pragma unroll
        for (int k = 0; k < 4; k++) LOAD_T(1018 - k, raw[k], yraw[k]);

        // 125 iters: steps G0..G124 (t=1022..523); loads G2..G126 (t>=515).
        #pragma unroll 1
        for (int g = 0; g < 125; ++g) {
            #pragma unroll
            for (int k = 0; k < 4; k++) PROC_B(raw[k], yraw[k], en0[k], en1[k]);
            const int tb = 1022 - 4 * (g + 2);
            #pragma unroll
            for (int k = 0; k < 4; k++) LOAD_T(tb - k, raw[k], yraw[k]);
            STEP(ee0[0], ee1[0], buf0, buf1, false);
            STEP(ee0[1], ee1[1], buf1, buf0, false);
            STEP(ee0[2], ee1[2], buf0, buf1, false);
            STEP(ee0[3], ee1[3], buf1, buf0, true);
            #pragma unroll
            for (int k = 0; k < 4; k++) { ee0[k] = en0[k]; ee1[k] = en1[k]; }
        }
        // ee = G125 (t=522..519); raws = G126 (t=518..515).
        #pragma unroll
        for (int k = 0; k < 4; k++) PROC_B(raw[k], yraw[k], en0[k], en1[k]);
        float2 rt2[2]; int yt2[2];
        LOAD_T(514, rt2[0], yt2[0]);
        LOAD_T(513, rt2[1], yt2[1]);
        STEP(ee0[0], ee1[0], buf0, buf1, false);
        STEP(ee0[1], ee1[1], buf1, buf0, false);
        STEP(ee0[2], ee1[2], buf0, buf1, false);
        STEP(ee0[3], ee1[3], buf1, buf0, true);
        float et0[2], et1[2];
        #pragma unroll
        for (int k = 0; k < 2; k++) PROC_B(rt2[k], yt2[k], et0[k], et1[k]);
        STEP(en0[0], en1[0], buf0, buf1, false);
        STEP(en0[1], en1[1], buf1, buf0, false);
        STEP(en0[2], en1[2], buf0, buf1, false);
        STEP(en0[3], en1[3], buf1, buf0, true);
        STEP(et0[0], et1[0], buf0, buf1, false);    // t = 514
        STEP(et0[1], et1[1], buf1, buf0, false);    // t = 513 -> c_513
        // missing transition (y_512, y_513): yprev == y_513 here.
        int y512 = __ldg(yr + 512);
        ts += tsh[y512 * 64 + yprev];
    }

    // ---- per-warp wrap-up ----
    M += __logf(pv);
    #pragma unroll
    for (int o = 16; o > 0; o >>= 1) point += __shfl_xor_sync(FULLMASK, point, o);
    if (l == 0) { sM[w] = M; sSc[w] = point + ts; }
    resbuf[w][l] = pk2(alo, ahi);
    __syncthreads();

    // ---- combine: warp 0 -> batch 2c, warp 1 -> batch 2c+1 ----
    if (w < 2) {
        float clo, chi;
        upk2(resbuf[w + 2][l], clo, chi);
        float prod = alo * clo + ahi * chi;       // d . c, lane partial
        #pragma unroll
        for (int o = 16; o > 0; o >>= 1) prod += __shfl_xor_sync(FULLMASK, prod, o);
        float loss = (sM[w] + sM[w + 2] + __logf(prod)) - (sSc[w] + sSc[w + 2]);
        if (l == 0) out[b] = loss;
    }
}

extern "C" void kernel_launch(void* const* d_in, const int* in_sizes, int n_in,
                              void* d_out, int out_size) {
    const float* y_pred = (const float*)d_in[0];   // [512,1024,64] f32
    const float* trans  = (const float*)d_in[1];   // [64,64] f32
    const int*   y_true = (const int*)d_in[2];     // [512,1024] i32
    float* out = (float*)d_out;                    // [512] f32
    (void)in_sizes; (void)n_in; (void)out_size;
    crf_fwd_kernel<<<256, 128>>>(y_pred, trans, y_true, out);
}